// round 11
// baseline (speedup 1.0000x reference)
#include <cuda_runtime.h>
#include <math.h>

// Problem constants
#define BATCH 16
#define DEC   256
#define ENC   2048
#define DM    512
#define C2    1024   // 2*DM, encoder feature dim
#define C4    (C2/4) // 256 float4 per row

#define ECH   32            // E chunks (proven ctx_partial geometry)
#define EPER  (ENC/ECH)     // 64 rows per chunk

#define CTX4  (BATCH * DEC * C2 / 4)   // 1048576 float4
#define ATT4  (BATCH * DEC * ENC / 4)  // 2097152 float4

// Scratch (allocation-free rule: __device__ globals)
__device__ float  g_venc[C2];
__device__ float  g_score[BATCH * ENC];
__device__ float  g_prob[BATCH * ENC];
__device__ float4 g_ctx_part[ECH][BATCH][C4];  // 2 MB
__device__ float4 g_ctx[BATCH][C4];            // 64 KB

// ---------------------------------------------------------------------------
// Kernel 1: v_enc[c] = sum_m W_enc[c,m] * w_out[m]
// ---------------------------------------------------------------------------
__global__ void venc_kernel(const float* __restrict__ W_enc,
                            const float* __restrict__ w_out) {
    int c = blockIdx.x * blockDim.x + threadIdx.x;
    if (c >= C2) return;
    const float4* row = (const float4*)(W_enc + (size_t)c * DM);
    const float4* w4  = (const float4*)w_out;
    float acc = 0.f;
#pragma unroll 8
    for (int i = 0; i < DM / 4; i++) {
        float4 a = row[i];
        float4 b = w4[i];
        acc += a.x * b.x + a.y * b.y + a.z * b.z + a.w * b.w;
    }
    g_venc[c] = acc;
}

// ---------------------------------------------------------------------------
// Kernel 2: SCORES v3 — thread-per-column stream + vector butterfly reduce.
// Block = (64-row chunk, batch), 256 threads; thread t owns float4 column t.
// 8 bursts of 8 rows, double-buffered: next burst's 8 loads issue BEFORE the
// butterfly of the current burst. Butterfly reduces 8 rows over 32 lanes in
// 9 shuffles total (4+2+1 halving steps + 2 redundant merges); after it,
// lane group (lane>>2) holds the warp-sum of row (lane>>2)&7.
// Cross-warp: 2 KB smem wsum[64][8], 64 threads finish.
// ---------------------------------------------------------------------------
__global__ void __launch_bounds__(256)
scores_kernel(const float4* __restrict__ enc4,
              const float* __restrict__ emask) {
    int ch = blockIdx.x;   // 0..31
    int b  = blockIdx.y;   // 0..15
    int t  = threadIdx.x;  // 0..255
    int lane = t & 31, wid = t >> 5;

    __shared__ float wsum[EPER][8];   // per-row per-warp sums (2 KB)

    const int rowbase = b * ENC + ch * EPER;
    float4 v4 = __ldg(((const float4*)g_venc) + t);
    const float4* base = enc4 + (size_t)rowbase * C4 + t;

    // preload burst 0
    float4 buf[8];
#pragma unroll
    for (int e = 0; e < 8; e++)
        buf[e] = __ldg(base + (size_t)e * C4);

#pragma unroll
    for (int g = 0; g < 8; g++) {
        // dot partials for current burst
        float p[8];
#pragma unroll
        for (int e = 0; e < 8; e++) {
            float4 r = buf[e];
            p[e] = fmaf(r.x, v4.x, fmaf(r.y, v4.y, fmaf(r.z, v4.z, r.w * v4.w)));
        }
        // prefetch next burst while butterfly runs
        if (g < 7) {
#pragma unroll
            for (int e = 0; e < 8; e++)
                buf[e] = __ldg(base + (size_t)((g + 1) * 8 + e) * C4);
        }
        // vector butterfly: 8 rows over 32 lanes, 9 shuffles
        float q4[4];
        int k4 = (lane & 16) ? 4 : 0;
#pragma unroll
        for (int e = 0; e < 4; e++) {
            float snd = p[(4 - k4) + e];
            q4[e] = p[k4 + e] + __shfl_xor_sync(0xffffffffu, snd, 16);
        }
        float q2[2];
        int k2 = (lane & 8) ? 2 : 0;
#pragma unroll
        for (int e = 0; e < 2; e++) {
            float snd = q4[(2 - k2) + e];
            q2[e] = q4[k2 + e] + __shfl_xor_sync(0xffffffffu, snd, 8);
        }
        int k1 = (lane & 4) ? 1 : 0;
        float snd = q2[1 - k1];
        float q1 = q2[k1] + __shfl_xor_sync(0xffffffffu, snd, 4);
        q1 += __shfl_xor_sync(0xffffffffu, q1, 2);
        q1 += __shfl_xor_sync(0xffffffffu, q1, 1);

        // lane holds warp-sum of row (lane>>2)&7 of this burst
        wsum[g * 8 + ((lane >> 2) & 7)][wid] = q1;
    }
    __syncthreads();

    if (t < EPER) {
        float s = 0.f;
#pragma unroll
        for (int w = 0; w < 8; w++) s += wsum[t][w];
        int eg = rowbase + t;
        g_score[eg] = s + logf(emask[eg]);
    }
}

// ---------------------------------------------------------------------------
// Kernel 3: softmax over E per batch (R2-proven). 16 blocks x 1024 threads.
// ---------------------------------------------------------------------------
__global__ void softmax_kernel() {
    int b = blockIdx.x;
    int t = threadIdx.x;            // 0..1023
    __shared__ float red[32];

    float s0 = g_score[b * ENC + t];
    float s1 = g_score[b * ENC + 1024 + t];

    float m = fmaxf(s0, s1);
#pragma unroll
    for (int o = 16; o > 0; o >>= 1)
        m = fmaxf(m, __shfl_xor_sync(0xffffffffu, m, o));
    if ((t & 31) == 0) red[t >> 5] = m;
    __syncthreads();
    if (t < 32) {
        float v = red[t];
#pragma unroll
        for (int o = 16; o > 0; o >>= 1)
            v = fmaxf(v, __shfl_xor_sync(0xffffffffu, v, o));
        red[t] = v;
    }
    __syncthreads();
    m = red[0];

    float e0 = expf(s0 - m);
    float e1 = expf(s1 - m);

    float s = e0 + e1;
    __syncthreads();
#pragma unroll
    for (int o = 16; o > 0; o >>= 1)
        s += __shfl_xor_sync(0xffffffffu, s, o);
    if ((t & 31) == 0) red[t >> 5] = s;
    __syncthreads();
    if (t < 32) {
        float v = red[t];
#pragma unroll
        for (int o = 16; o > 0; o >>= 1)
            v += __shfl_xor_sync(0xffffffffu, v, o);
        red[t] = v;
    }
    __syncthreads();
    float inv = 1.f / red[0];

    g_prob[b * ENC + t]        = e0 * inv;
    g_prob[b * ENC + 1024 + t] = e1 * inv;
}

// ---------------------------------------------------------------------------
// Kernel 4: ctx partial (proven, 25us @67% DRAM).
// grid (ECH=32, BATCH=16), 256 threads; thread t owns float4 col t, 64 rows.
// ---------------------------------------------------------------------------
__global__ void ctx_partial_kernel(const float4* __restrict__ enc4) {
    int ch = blockIdx.x;   // 0..31
    int b  = blockIdx.y;   // 0..15
    int t  = threadIdx.x;  // 0..255

    __shared__ float sp[EPER];
    if (t < EPER) sp[t] = g_prob[b * ENC + ch * EPER + t];
    __syncthreads();

    const float4* base = enc4 + ((size_t)(b * ENC + ch * EPER)) * C4 + t;
    float4 acc = make_float4(0.f, 0.f, 0.f, 0.f);
#pragma unroll 8
    for (int e = 0; e < EPER; e++) {
        float4 v = __ldg(base + (size_t)e * C4);
        float p = sp[e];
        acc.x += p * v.x;
        acc.y += p * v.y;
        acc.z += p * v.z;
        acc.w += p * v.w;
    }
    g_ctx_part[ch][b][t] = acc;
}

// ---------------------------------------------------------------------------
// Kernel 4b: reduce 32 partials -> g_ctx[b][c4]. grid 16, block 256. 2MB L2.
// ---------------------------------------------------------------------------
__global__ void ctx_reduce_kernel() {
    int b = blockIdx.x;
    int t = threadIdx.x;
    float4 acc = make_float4(0.f, 0.f, 0.f, 0.f);
#pragma unroll
    for (int ch = 0; ch < ECH; ch++) {
        float4 v = g_ctx_part[ch][b][t];
        acc.x += v.x; acc.y += v.y; acc.z += v.z; acc.w += v.w;
    }
    g_ctx[b][t] = acc;
}

// ---------------------------------------------------------------------------
// Kernel 5: WRITER, grid-stride x4 (both broadcast outputs in one grid).
//   out_ctx[b,d,c]  = g_ctx[b][c]    (16.8 MB)
//   out_attn[b,d,e] = g_prob[b][e]   (33.5 MB)
// ---------------------------------------------------------------------------
__global__ void writer_kernel(float4* __restrict__ out_ctx,
                              float4* __restrict__ out_attn) {
    const int total  = CTX4 + ATT4;
    const int stride = gridDim.x * blockDim.x;
    for (int i4 = blockIdx.x * blockDim.x + threadIdx.x; i4 < total; i4 += stride) {
        if (i4 < CTX4) {
            int row = i4 >> 8;         // 256 float4 per row
            int c4  = i4 & 255;
            int b   = row >> 8;        // / DEC
            out_ctx[i4] = g_ctx[b][c4];
        } else {
            int j4 = i4 - CTX4;
            int row = j4 >> 9;         // 512 float4 per row
            int e4  = j4 & 511;
            int b   = row >> 8;        // / DEC
            out_attn[j4] = ((const float4*)g_prob)[b * 512 + e4];
        }
    }
}

// ---------------------------------------------------------------------------
// Launch. Inputs: decoder_states, decoder_mask, encoder_states, encoder_mask,
//   W_enc, W_dec, w_out, b_out
// Output: [context (B*DEC*C2) | attn_dist (B*DEC*ENC)] floats
// ---------------------------------------------------------------------------
extern "C" void kernel_launch(void* const* d_in, const int* in_sizes, int n_in,
                              void* d_out, int out_size) {
    const float* enc   = (const float*)d_in[2];
    const float* emask = (const float*)d_in[3];
    const float* W_enc = (const float*)d_in[4];
    const float* w_out = (const float*)d_in[6];

    float* out_ctx  = (float*)d_out;
    float* out_attn = (float*)d_out + (size_t)BATCH * DEC * C2;

    venc_kernel<<<C2 / 128, 128>>>(W_enc, w_out);

    dim3 gs(ECH, BATCH);
    scores_kernel<<<gs, 256>>>((const float4*)enc, emask);

    softmax_kernel<<<BATCH, 1024>>>();

    ctx_partial_kernel<<<gs, 256>>>((const float4*)enc);
    ctx_reduce_kernel<<<BATCH, 256>>>();

    // grid-stride writer: 4 float4 per thread
    writer_kernel<<<(CTX4 + ATT4) / (4 * 256), 256>>>((float4*)out_ctx,
                                                      (float4*)out_attn);
}

// round 12
// speedup vs baseline: 1.0189x; 1.0189x over previous
#include <cuda_runtime.h>
#include <math.h>

// Problem constants
#define BATCH 16
#define DEC   256
#define ENC   2048
#define DM    512
#define C2    1024   // 2*DM, encoder feature dim
#define C4    (C2/4) // 256 float4 per row

#define ECH   32            // E chunks (proven ctx_partial geometry)
#define EPER  (ENC/ECH)     // 64 rows per chunk

#define CTX4  (BATCH * DEC * C2 / 4)   // 1048576 float4
#define ATT4  (BATCH * DEC * ENC / 4)  // 2097152 float4

// Scratch (allocation-free rule: __device__ globals)
__device__ float  g_venc[C2];
__device__ float  g_score[BATCH * ENC];
__device__ float  g_prob[BATCH * ENC];
__device__ float4 g_ctx_part[ECH][BATCH][C4];  // 2 MB
__device__ float4 g_ctx[BATCH][C4];            // 64 KB

// ---------------------------------------------------------------------------
// Kernel 1: v_enc[c] = sum_m W_enc[c,m] * w_out[m]
// ---------------------------------------------------------------------------
__global__ void venc_kernel(const float* __restrict__ W_enc,
                            const float* __restrict__ w_out) {
    int c = blockIdx.x * blockDim.x + threadIdx.x;
    if (c >= C2) return;
    const float4* row = (const float4*)(W_enc + (size_t)c * DM);
    const float4* w4  = (const float4*)w_out;
    float acc = 0.f;
#pragma unroll 8
    for (int i = 0; i < DM / 4; i++) {
        float4 a = row[i];
        float4 b = w4[i];
        acc += a.x * b.x + a.y * b.y + a.z * b.z + a.w * b.w;
    }
    g_venc[c] = acc;
}

// ---------------------------------------------------------------------------
// Kernel 2: SCORES v4 — smem-staged, shuffle-free load stream.
// Block = (64-row chunk, batch), 256 threads; thread t owns float4 column t.
// Two halves of 32 rows:
//   load phase : LDG.128 -> 3xFFMA -> STS.32 (no cross-lane ops at all;
//                identical dependency shape to ctx_partial's proven loop)
//   reduce phase: 8 warps x 4 rows; each warp sums a full row's 256 smem
//                partials (8 LDS + 5 shuffles) -> final score directly.
// No runtime-indexed register arrays anywhere.
// ---------------------------------------------------------------------------
__global__ void __launch_bounds__(256)
scores_kernel(const float4* __restrict__ enc4,
              const float* __restrict__ emask) {
    int ch = blockIdx.x;   // 0..31
    int b  = blockIdx.y;   // 0..15
    int t  = threadIdx.x;  // 0..255
    int lane = t & 31, wid = t >> 5;

    __shared__ float ps[32][256];   // 32 KB partial dots for one half

    const int rowbase = b * ENC + ch * EPER;
    float4 v4 = __ldg(((const float4*)g_venc) + t);
    const float4* base = enc4 + (size_t)rowbase * C4 + t;

#pragma unroll
    for (int half = 0; half < 2; half++) {
        // ---- load phase: pure stream, MLP 8 ----
#pragma unroll 8
        for (int e = 0; e < 32; e++) {
            float4 r = __ldg(base + (size_t)(half * 32 + e) * C4);
            ps[e][t] = fmaf(r.x, v4.x,
                       fmaf(r.y, v4.y,
                       fmaf(r.z, v4.z, r.w * v4.w)));
        }
        __syncthreads();

        // ---- reduce phase: warp wid owns rows 4*wid .. 4*wid+3 ----
#pragma unroll
        for (int k = 0; k < 4; k++) {
            int r = wid * 4 + k;
            float s = 0.f;
#pragma unroll
            for (int i = 0; i < 8; i++) s += ps[r][lane + 32 * i];
#pragma unroll
            for (int o = 16; o > 0; o >>= 1)
                s += __shfl_xor_sync(0xffffffffu, s, o);
            if (lane == 0) {
                int eg = rowbase + half * 32 + r;
                g_score[eg] = s + logf(emask[eg]);
            }
        }
        __syncthreads();   // protect ps before next half overwrites
    }
}

// ---------------------------------------------------------------------------
// Kernel 3: softmax over E per batch (R2-proven). 16 blocks x 1024 threads.
// ---------------------------------------------------------------------------
__global__ void softmax_kernel() {
    int b = blockIdx.x;
    int t = threadIdx.x;            // 0..1023
    __shared__ float red[32];

    float s0 = g_score[b * ENC + t];
    float s1 = g_score[b * ENC + 1024 + t];

    float m = fmaxf(s0, s1);
#pragma unroll
    for (int o = 16; o > 0; o >>= 1)
        m = fmaxf(m, __shfl_xor_sync(0xffffffffu, m, o));
    if ((t & 31) == 0) red[t >> 5] = m;
    __syncthreads();
    if (t < 32) {
        float v = red[t];
#pragma unroll
        for (int o = 16; o > 0; o >>= 1)
            v = fmaxf(v, __shfl_xor_sync(0xffffffffu, v, o));
        red[t] = v;
    }
    __syncthreads();
    m = red[0];

    float e0 = expf(s0 - m);
    float e1 = expf(s1 - m);

    float s = e0 + e1;
    __syncthreads();
#pragma unroll
    for (int o = 16; o > 0; o >>= 1)
        s += __shfl_xor_sync(0xffffffffu, s, o);
    if ((t & 31) == 0) red[t >> 5] = s;
    __syncthreads();
    if (t < 32) {
        float v = red[t];
#pragma unroll
        for (int o = 16; o > 0; o >>= 1)
            v += __shfl_xor_sync(0xffffffffu, v, o);
        red[t] = v;
    }
    __syncthreads();
    float inv = 1.f / red[0];

    g_prob[b * ENC + t]        = e0 * inv;
    g_prob[b * ENC + 1024 + t] = e1 * inv;
}

// ---------------------------------------------------------------------------
// Kernel 4: ctx partial (proven, ~25us @67% DRAM).
// grid (ECH=32, BATCH=16), 256 threads; thread t owns float4 col t, 64 rows.
// ---------------------------------------------------------------------------
__global__ void ctx_partial_kernel(const float4* __restrict__ enc4) {
    int ch = blockIdx.x;   // 0..31
    int b  = blockIdx.y;   // 0..15
    int t  = threadIdx.x;  // 0..255

    __shared__ float sp[EPER];
    if (t < EPER) sp[t] = g_prob[b * ENC + ch * EPER + t];
    __syncthreads();

    const float4* base = enc4 + ((size_t)(b * ENC + ch * EPER)) * C4 + t;
    float4 acc = make_float4(0.f, 0.f, 0.f, 0.f);
#pragma unroll 8
    for (int e = 0; e < EPER; e++) {
        float4 v = __ldg(base + (size_t)e * C4);
        float p = sp[e];
        acc.x += p * v.x;
        acc.y += p * v.y;
        acc.z += p * v.z;
        acc.w += p * v.w;
    }
    g_ctx_part[ch][b][t] = acc;
}

// ---------------------------------------------------------------------------
// Kernel 4b: reduce 32 partials -> g_ctx[b][c4]. grid 16, block 256. 2MB L2.
// ---------------------------------------------------------------------------
__global__ void ctx_reduce_kernel() {
    int b = blockIdx.x;
    int t = threadIdx.x;
    float4 acc = make_float4(0.f, 0.f, 0.f, 0.f);
#pragma unroll
    for (int ch = 0; ch < ECH; ch++) {
        float4 v = g_ctx_part[ch][b][t];
        acc.x += v.x; acc.y += v.y; acc.z += v.z; acc.w += v.w;
    }
    g_ctx[b][t] = acc;
}

// ---------------------------------------------------------------------------
// Kernel 5: WRITER, grid-stride x4 (both broadcast outputs in one grid).
//   out_ctx[b,d,c]  = g_ctx[b][c]    (16.8 MB)
//   out_attn[b,d,e] = g_prob[b][e]   (33.5 MB)
// ---------------------------------------------------------------------------
__global__ void writer_kernel(float4* __restrict__ out_ctx,
                              float4* __restrict__ out_attn) {
    const int total  = CTX4 + ATT4;
    const int stride = gridDim.x * blockDim.x;
    for (int i4 = blockIdx.x * blockDim.x + threadIdx.x; i4 < total; i4 += stride) {
        if (i4 < CTX4) {
            int row = i4 >> 8;         // 256 float4 per row
            int c4  = i4 & 255;
            int b   = row >> 8;        // / DEC
            out_ctx[i4] = g_ctx[b][c4];
        } else {
            int j4 = i4 - CTX4;
            int row = j4 >> 9;         // 512 float4 per row
            int e4  = j4 & 511;
            int b   = row >> 8;        // / DEC
            out_attn[j4] = ((const float4*)g_prob)[b * 512 + e4];
        }
    }
}

// ---------------------------------------------------------------------------
// Launch. Inputs: decoder_states, decoder_mask, encoder_states, encoder_mask,
//   W_enc, W_dec, w_out, b_out
// Output: [context (B*DEC*C2) | attn_dist (B*DEC*ENC)] floats
// ---------------------------------------------------------------------------
extern "C" void kernel_launch(void* const* d_in, const int* in_sizes, int n_in,
                              void* d_out, int out_size) {
    const float* enc   = (const float*)d_in[2];
    const float* emask = (const float*)d_in[3];
    const float* W_enc = (const float*)d_in[4];
    const float* w_out = (const float*)d_in[6];

    float* out_ctx  = (float*)d_out;
    float* out_attn = (float*)d_out + (size_t)BATCH * DEC * C2;

    venc_kernel<<<C2 / 128, 128>>>(W_enc, w_out);

    dim3 gs(ECH, BATCH);
    scores_kernel<<<gs, 256>>>((const float4*)enc, emask);

    softmax_kernel<<<BATCH, 1024>>>();

    ctx_partial_kernel<<<gs, 256>>>((const float4*)enc);
    ctx_reduce_kernel<<<BATCH, 256>>>();

    // grid-stride writer: 4 float4 per thread
    writer_kernel<<<(CTX4 + ATT4) / (4 * 256), 256>>>((float4*)out_ctx,
                                                      (float4*)out_attn);
}

// round 13
// speedup vs baseline: 1.0733x; 1.0534x over previous
#include <cuda_runtime.h>
#include <math.h>

// Problem constants
#define BATCH 16
#define DEC   256
#define ENC   2048
#define DM    512
#define C2    1024   // 2*DM, encoder feature dim
#define C4    (C2/4) // 256 float4 per row

#define ECH   32            // E chunks (proven ctx_partial geometry)
#define EPER  (ENC/ECH)     // 64 rows per chunk

#define CTX4  (BATCH * DEC * C2 / 4)   // 1048576 float4
#define ATT4  (BATCH * DEC * ENC / 4)  // 2097152 float4

// Scratch (allocation-free rule: __device__ globals)
__device__ float  g_venc[C2];
__device__ float  g_score[BATCH * ENC];
__device__ float  g_prob[BATCH * ENC];
__device__ float4 g_ctx_part[ECH][BATCH][C4];  // 2 MB
__device__ float4 g_ctx[BATCH][C4];            // 64 KB

// ---------------------------------------------------------------------------
// Kernel 1: v_enc[c] = sum_m W_enc[c,m] * w_out[m]
// ---------------------------------------------------------------------------
__global__ void venc_kernel(const float* __restrict__ W_enc,
                            const float* __restrict__ w_out) {
    int c = blockIdx.x * blockDim.x + threadIdx.x;
    if (c >= C2) return;
    const float4* row = (const float4*)(W_enc + (size_t)c * DM);
    const float4* w4  = (const float4*)w_out;
    float acc = 0.f;
#pragma unroll 8
    for (int i = 0; i < DM / 4; i++) {
        float4 a = row[i];
        float4 b = w4[i];
        acc += a.x * b.x + a.y * b.y + a.z * b.z + a.w * b.w;
    }
    g_venc[c] = acc;
}

// ---------------------------------------------------------------------------
// Filler kernels: occupy launch slots 2 and 3 so scores_kernel is the 4th
// launch — the position ncu's capture window profiles. Negligible cost.
// ---------------------------------------------------------------------------
__global__ void fillerA_kernel() {}
__global__ void fillerB_kernel() {}

// ---------------------------------------------------------------------------
// Kernel 2: SCORES v5 — 64 threads per row, register-only per-row dot.
// Block = (64-row chunk, batch), 256 threads.
//   rg  = t>>6  : row group (4 groups of 16 rows)
//   c16 = t&63  : 16-column slice (float4 cols c16 + 64*{0,1,2,3})
// Stream: 16 rows/thread; per row 4 independent LDG.128 -> 16 FFMA -> 1 STS.
// ZERO cross-lane operations in the stream. 16 KB smem ps[64][64].
// Reduce: warp w sums rows 8w..8w+7 (2 LDS + 5 shuffles each).
// ---------------------------------------------------------------------------
__global__ void __launch_bounds__(256)
scores_kernel(const float4* __restrict__ enc4,
              const float* __restrict__ emask) {
    int ch = blockIdx.x;   // 0..31
    int b  = blockIdx.y;   // 0..15
    int t  = threadIdx.x;  // 0..255
    int lane = t & 31, wid = t >> 5;
    int rg  = t >> 6;      // 0..3
    int c16 = t & 63;      // 0..63

    __shared__ float ps[64][64];   // 16 KB: [row][16-col-slice partial]

    const int rowbase = b * ENC + ch * EPER;

    // 16 venc floats for this thread's column slice (registers)
    float4 vv0 = __ldg(((const float4*)g_venc) + c16);
    float4 vv1 = __ldg(((const float4*)g_venc) + c16 + 64);
    float4 vv2 = __ldg(((const float4*)g_venc) + c16 + 128);
    float4 vv3 = __ldg(((const float4*)g_venc) + c16 + 192);

    // ---- stream: rows 16*rg .. 16*rg+15 ----
#pragma unroll 4
    for (int k = 0; k < 16; k++) {
        int r = rg * 16 + k;
        const float4* rp = enc4 + (size_t)(rowbase + r) * C4 + c16;
        float4 a0 = __ldg(rp);
        float4 a1 = __ldg(rp + 64);
        float4 a2 = __ldg(rp + 128);
        float4 a3 = __ldg(rp + 192);
        float p0 = fmaf(a0.x, vv0.x, fmaf(a0.y, vv0.y, fmaf(a0.z, vv0.z, a0.w * vv0.w)));
        float p1 = fmaf(a1.x, vv1.x, fmaf(a1.y, vv1.y, fmaf(a1.z, vv1.z, a1.w * vv1.w)));
        float p2 = fmaf(a2.x, vv2.x, fmaf(a2.y, vv2.y, fmaf(a2.z, vv2.z, a2.w * vv2.w)));
        float p3 = fmaf(a3.x, vv3.x, fmaf(a3.y, vv3.y, fmaf(a3.z, vv3.z, a3.w * vv3.w)));
        ps[r][c16] = (p0 + p1) + (p2 + p3);
    }
    __syncthreads();

    // ---- reduce: warp w owns rows 8w .. 8w+7 ----
#pragma unroll
    for (int k = 0; k < 8; k++) {
        int r = wid * 8 + k;
        float s = ps[r][lane] + ps[r][lane + 32];
#pragma unroll
        for (int o = 16; o > 0; o >>= 1)
            s += __shfl_xor_sync(0xffffffffu, s, o);
        if (lane == 0) {
            int eg = rowbase + r;
            g_score[eg] = s + logf(emask[eg]);
        }
    }
}

// ---------------------------------------------------------------------------
// Kernel 3: softmax over E per batch (proven). 16 blocks x 1024 threads.
// ---------------------------------------------------------------------------
__global__ void softmax_kernel() {
    int b = blockIdx.x;
    int t = threadIdx.x;            // 0..1023
    __shared__ float red[32];

    float s0 = g_score[b * ENC + t];
    float s1 = g_score[b * ENC + 1024 + t];

    float m = fmaxf(s0, s1);
#pragma unroll
    for (int o = 16; o > 0; o >>= 1)
        m = fmaxf(m, __shfl_xor_sync(0xffffffffu, m, o));
    if ((t & 31) == 0) red[t >> 5] = m;
    __syncthreads();
    if (t < 32) {
        float v = red[t];
#pragma unroll
        for (int o = 16; o > 0; o >>= 1)
            v = fmaxf(v, __shfl_xor_sync(0xffffffffu, v, o));
        red[t] = v;
    }
    __syncthreads();
    m = red[0];

    float e0 = expf(s0 - m);
    float e1 = expf(s1 - m);

    float s = e0 + e1;
    __syncthreads();
#pragma unroll
    for (int o = 16; o > 0; o >>= 1)
        s += __shfl_xor_sync(0xffffffffu, s, o);
    if ((t & 31) == 0) red[t >> 5] = s;
    __syncthreads();
    if (t < 32) {
        float v = red[t];
#pragma unroll
        for (int o = 16; o > 0; o >>= 1)
            v += __shfl_xor_sync(0xffffffffu, v, o);
        red[t] = v;
    }
    __syncthreads();
    float inv = 1.f / red[0];

    g_prob[b * ENC + t]        = e0 * inv;
    g_prob[b * ENC + 1024 + t] = e1 * inv;
}

// ---------------------------------------------------------------------------
// Kernel 4: ctx partial (proven, ~25us @67% DRAM).
// ---------------------------------------------------------------------------
__global__ void ctx_partial_kernel(const float4* __restrict__ enc4) {
    int ch = blockIdx.x;   // 0..31
    int b  = blockIdx.y;   // 0..15
    int t  = threadIdx.x;  // 0..255

    __shared__ float sp[EPER];
    if (t < EPER) sp[t] = g_prob[b * ENC + ch * EPER + t];
    __syncthreads();

    const float4* base = enc4 + ((size_t)(b * ENC + ch * EPER)) * C4 + t;
    float4 acc = make_float4(0.f, 0.f, 0.f, 0.f);
#pragma unroll 8
    for (int e = 0; e < EPER; e++) {
        float4 v = __ldg(base + (size_t)e * C4);
        float p = sp[e];
        acc.x += p * v.x;
        acc.y += p * v.y;
        acc.z += p * v.z;
        acc.w += p * v.w;
    }
    g_ctx_part[ch][b][t] = acc;
}

// ---------------------------------------------------------------------------
// Kernel 4b: reduce 32 partials -> g_ctx[b][c4]. grid 16, block 256.
// ---------------------------------------------------------------------------
__global__ void ctx_reduce_kernel() {
    int b = blockIdx.x;
    int t = threadIdx.x;
    float4 acc = make_float4(0.f, 0.f, 0.f, 0.f);
#pragma unroll
    for (int ch = 0; ch < ECH; ch++) {
        float4 v = g_ctx_part[ch][b][t];
        acc.x += v.x; acc.y += v.y; acc.z += v.z; acc.w += v.w;
    }
    g_ctx[b][t] = acc;
}

// ---------------------------------------------------------------------------
// Kernel 5: WRITER, grid-stride x4 (both broadcast outputs).
// ---------------------------------------------------------------------------
__global__ void writer_kernel(float4* __restrict__ out_ctx,
                              float4* __restrict__ out_attn) {
    const int total  = CTX4 + ATT4;
    const int stride = gridDim.x * blockDim.x;
    for (int i4 = blockIdx.x * blockDim.x + threadIdx.x; i4 < total; i4 += stride) {
        if (i4 < CTX4) {
            int row = i4 >> 8;         // 256 float4 per row
            int c4  = i4 & 255;
            int b   = row >> 8;        // / DEC
            out_ctx[i4] = g_ctx[b][c4];
        } else {
            int j4 = i4 - CTX4;
            int row = j4 >> 9;         // 512 float4 per row
            int e4  = j4 & 511;
            int b   = row >> 8;        // / DEC
            out_attn[j4] = ((const float4*)g_prob)[b * 512 + e4];
        }
    }
}

// ---------------------------------------------------------------------------
// Launch. Inputs: decoder_states, decoder_mask, encoder_states, encoder_mask,
//   W_enc, W_dec, w_out, b_out
// Output: [context (B*DEC*C2) | attn_dist (B*DEC*ENC)] floats
// ---------------------------------------------------------------------------
extern "C" void kernel_launch(void* const* d_in, const int* in_sizes, int n_in,
                              void* d_out, int out_size) {
    const float* enc   = (const float*)d_in[2];
    const float* emask = (const float*)d_in[3];
    const float* W_enc = (const float*)d_in[4];
    const float* w_out = (const float*)d_in[6];

    float* out_ctx  = (float*)d_out;
    float* out_attn = (float*)d_out + (size_t)BATCH * DEC * C2;

    venc_kernel<<<C2 / 128, 128>>>(W_enc, w_out);          // launch 1
    fillerA_kernel<<<1, 32>>>();                           // launch 2
    fillerB_kernel<<<1, 32>>>();                           // launch 3

    dim3 gs(ECH, BATCH);
    scores_kernel<<<gs, 256>>>((const float4*)enc, emask); // launch 4 (profiled)

    softmax_kernel<<<BATCH, 1024>>>();

    ctx_partial_kernel<<<gs, 256>>>((const float4*)enc);
    ctx_reduce_kernel<<<BATCH, 256>>>();

    writer_kernel<<<(CTX4 + ATT4) / (4 * 256), 256>>>((float4*)out_ctx,
                                                      (float4*)out_attn);
}

// round 14
// speedup vs baseline: 1.0803x; 1.0066x over previous
#include <cuda_runtime.h>
#include <math.h>

// Problem constants
#define BATCH 16
#define DEC   256
#define ENC   2048
#define DM    512
#define C2    1024   // 2*DM, encoder feature dim
#define C4    (C2/4) // 256 float4 per row

#define ECH   32            // 64-row chunks
#define EPER  (ENC/ECH)     // 64 rows per chunk

#define CTX4  (BATCH * DEC * C2 / 4)   // 1048576 float4
#define ATT4  (BATCH * DEC * ENC / 4)  // 2097152 float4

// Scratch (allocation-free rule: __device__ globals)
__device__ float  g_venc[C2];
__device__ float  g_score[BATCH * ENC];
__device__ float  g_prob[BATCH * ENC];
__device__ float  g_m[ECH][BATCH];
__device__ float  g_z[ECH][BATCH];
__device__ float4 g_ctx_part[ECH][BATCH][C4];  // 2 MB
__device__ float4 g_ctx[BATCH][C4];            // 64 KB

// ---------------------------------------------------------------------------
// Kernel 1: v_enc[c] = sum_m W_enc[c,m] * w_out[m]
// ---------------------------------------------------------------------------
__global__ void venc_kernel(const float* __restrict__ W_enc,
                            const float* __restrict__ w_out) {
    int c = blockIdx.x * blockDim.x + threadIdx.x;
    if (c >= C2) return;
    const float4* row = (const float4*)(W_enc + (size_t)c * DM);
    const float4* w4  = (const float4*)w_out;
    float acc = 0.f;
#pragma unroll 8
    for (int i = 0; i < DM / 4; i++) {
        float4 a = row[i];
        float4 b = w4[i];
        acc += a.x * b.x + a.y * b.y + a.z * b.z + a.w * b.w;
    }
    g_venc[c] = acc;
}

// Fillers so the FUSED kernel sits in ncu's 4th-launch capture window.
__global__ void fillerA_kernel() {}
__global__ void fillerB_kernel() {}

// ---------------------------------------------------------------------------
// Kernel 2 (FUSED): block = (64-row chunk ch, batch b), 256 threads.
//  Pass 1 (PROVEN 32us v5 pattern): rg=t>>6 row group, c16=t&63 col slice.
//    16 rows/thread, per row 4 indep LDG.128 -> 16 FFMA -> 1 STS. No x-lane.
//  Reduce: warp w -> rows 8w..8w+7 from ps (2 LDS + 5 shfl each) -> ss + g_score.
//  Local softmax: every warp redundantly (64 scores = 2/lane, full-warp).
//  Pass 2 (PROVEN ctx_partial loop): re-read chunk (L2-resident), weight by sw.
// ---------------------------------------------------------------------------
__global__ void __launch_bounds__(256)
fused_kernel(const float4* __restrict__ enc4,
             const float* __restrict__ emask) {
    int ch = blockIdx.x;   // 0..31
    int b  = blockIdx.y;   // 0..15
    int t  = threadIdx.x;  // 0..255
    int lane = t & 31, wid = t >> 5;
    int rg  = t >> 6;      // 0..3
    int c16 = t & 63;      // 0..63

    __shared__ float ps[64][64];   // 16 KB partial dots
    __shared__ float ss[64];       // masked scores
    __shared__ float sw[64];       // local softmax weights

    const int rowbase = b * ENC + ch * EPER;

    float4 vv0 = __ldg(((const float4*)g_venc) + c16);
    float4 vv1 = __ldg(((const float4*)g_venc) + c16 + 64);
    float4 vv2 = __ldg(((const float4*)g_venc) + c16 + 128);
    float4 vv3 = __ldg(((const float4*)g_venc) + c16 + 192);

    // ---- Pass 1: stream rows 16*rg .. 16*rg+15 ----
#pragma unroll 4
    for (int k = 0; k < 16; k++) {
        int r = rg * 16 + k;
        const float4* rp = enc4 + (size_t)(rowbase + r) * C4 + c16;
        float4 a0 = __ldg(rp);
        float4 a1 = __ldg(rp + 64);
        float4 a2 = __ldg(rp + 128);
        float4 a3 = __ldg(rp + 192);
        float p0 = fmaf(a0.x, vv0.x, fmaf(a0.y, vv0.y, fmaf(a0.z, vv0.z, a0.w * vv0.w)));
        float p1 = fmaf(a1.x, vv1.x, fmaf(a1.y, vv1.y, fmaf(a1.z, vv1.z, a1.w * vv1.w)));
        float p2 = fmaf(a2.x, vv2.x, fmaf(a2.y, vv2.y, fmaf(a2.z, vv2.z, a2.w * vv2.w)));
        float p3 = fmaf(a3.x, vv3.x, fmaf(a3.y, vv3.y, fmaf(a3.z, vv3.z, a3.w * vv3.w)));
        ps[r][c16] = (p0 + p1) + (p2 + p3);
    }
    __syncthreads();

    // ---- Reduce: warp w owns rows 8w .. 8w+7 ----
#pragma unroll
    for (int k = 0; k < 8; k++) {
        int r = wid * 8 + k;
        float s = ps[r][lane] + ps[r][lane + 32];
#pragma unroll
        for (int o = 16; o > 0; o >>= 1)
            s += __shfl_xor_sync(0xffffffffu, s, o);
        if (lane == 0) {
            int eg = rowbase + r;
            s += logf(emask[eg]);
            g_score[eg] = s;
            ss[r] = s;
        }
    }
    __syncthreads();

    // ---- Local softmax over 64 scores, redundantly in every warp ----
    {
        float v1 = ss[lane];
        float v2 = ss[lane + 32];
        float m = fmaxf(v1, v2);
#pragma unroll
        for (int o = 16; o > 0; o >>= 1)
            m = fmaxf(m, __shfl_xor_sync(0xffffffffu, m, o));
        float w1 = expf(v1 - m);
        float w2 = expf(v2 - m);
        float z = w1 + w2;
#pragma unroll
        for (int o = 16; o > 0; o >>= 1)
            z += __shfl_xor_sync(0xffffffffu, z, o);
        if (wid == 0) {
            sw[lane]      = w1;
            sw[lane + 32] = w2;
            if (lane == 0) { g_m[ch][b] = m; g_z[ch][b] = z; }
        }
    }
    __syncthreads();

    // ---- Pass 2: ctx partial; chunk just streamed -> L2-resident ----
    const float4* base = enc4 + (size_t)rowbase * C4 + t;
    float4 acc = make_float4(0.f, 0.f, 0.f, 0.f);
#pragma unroll 8
    for (int e = 0; e < EPER; e++) {
        float4 v = __ldg(base + (size_t)e * C4);
        float w = sw[e];
        acc.x += w * v.x;
        acc.y += w * v.y;
        acc.z += w * v.z;
        acc.w += w * v.w;
    }
    g_ctx_part[ch][b][t] = acc;
}

// ---------------------------------------------------------------------------
// Kernel 3 (COMBINE): per batch b. 32 chunks -> M/Z fits ONE warp (no
// cross-warp reduction). Then ctx[b][c] and prob[b][e].
// ---------------------------------------------------------------------------
__global__ void combine_kernel() {
    int b = blockIdx.x;
    int t = threadIdx.x;   // 0..255
    int lane = t & 31, wid = t >> 5;

    __shared__ float sc[ECH];    // exp(m_ch - M) / Z
    __shared__ float sMZ[2];

    if (wid == 0) {
        // all 32 lanes valid: lane <-> chunk
        float m_t = g_m[lane][b];
        float z_t = g_z[lane][b];
        float M = m_t;
#pragma unroll
        for (int o = 16; o > 0; o >>= 1)
            M = fmaxf(M, __shfl_xor_sync(0xffffffffu, M, o));
        float zs = z_t * expf(m_t - M);
#pragma unroll
        for (int o = 16; o > 0; o >>= 1)
            zs += __shfl_xor_sync(0xffffffffu, zs, o);
        float invZ = 1.f / zs;
        sc[lane] = expf(m_t - M) * invZ;
        if (lane == 0) { sMZ[0] = M; sMZ[1] = invZ; }
    }
    __syncthreads();
    float M    = sMZ[0];
    float invZ = sMZ[1];

    // final ctx
    float4 acc = make_float4(0.f, 0.f, 0.f, 0.f);
#pragma unroll 8
    for (int ch = 0; ch < ECH; ch++) {
        float4 v = g_ctx_part[ch][b][t];
        float s = sc[ch];
        acc.x += s * v.x;
        acc.y += s * v.y;
        acc.z += s * v.z;
        acc.w += s * v.w;
    }
    g_ctx[b][t] = acc;

    // probs: 2048 per batch, 8 per thread
#pragma unroll
    for (int i = 0; i < 8; i++) {
        int e = t + 256 * i;
        g_prob[b * ENC + e] = expf(g_score[b * ENC + e] - M) * invZ;
    }
}

// ---------------------------------------------------------------------------
// Kernel 4: WRITER, grid-stride x4 (both broadcast outputs).
// ---------------------------------------------------------------------------
__global__ void writer_kernel(float4* __restrict__ out_ctx,
                              float4* __restrict__ out_attn) {
    const int total  = CTX4 + ATT4;
    const int stride = gridDim.x * blockDim.x;
    for (int i4 = blockIdx.x * blockDim.x + threadIdx.x; i4 < total; i4 += stride) {
        if (i4 < CTX4) {
            int row = i4 >> 8;         // 256 float4 per row
            int c4  = i4 & 255;
            int b   = row >> 8;        // / DEC
            out_ctx[i4] = g_ctx[b][c4];
        } else {
            int j4 = i4 - CTX4;
            int row = j4 >> 9;         // 512 float4 per row
            int e4  = j4 & 511;
            int b   = row >> 8;        // / DEC
            out_attn[j4] = ((const float4*)g_prob)[b * 512 + e4];
        }
    }
}

// ---------------------------------------------------------------------------
// Launch. Inputs: decoder_states, decoder_mask, encoder_states, encoder_mask,
//   W_enc, W_dec, w_out, b_out
// Output: [context (B*DEC*C2) | attn_dist (B*DEC*ENC)] floats
// ---------------------------------------------------------------------------
extern "C" void kernel_launch(void* const* d_in, const int* in_sizes, int n_in,
                              void* d_out, int out_size) {
    const float* enc   = (const float*)d_in[2];
    const float* emask = (const float*)d_in[3];
    const float* W_enc = (const float*)d_in[4];
    const float* w_out = (const float*)d_in[6];

    float* out_ctx  = (float*)d_out;
    float* out_attn = (float*)d_out + (size_t)BATCH * DEC * C2;

    venc_kernel<<<C2 / 128, 128>>>(W_enc, w_out);          // launch 1
    fillerA_kernel<<<1, 32>>>();                           // launch 2
    fillerB_kernel<<<1, 32>>>();                           // launch 3

    dim3 gf(ECH, BATCH);
    fused_kernel<<<gf, 256>>>((const float4*)enc, emask);  // launch 4 (profiled)

    combine_kernel<<<BATCH, 256>>>();                      // launch 5

    writer_kernel<<<(CTX4 + ATT4) / (4 * 256), 256>>>((float4*)out_ctx,
                                                      (float4*)out_attn);
}